// round 12
// baseline (speedup 1.0000x reference)
#include <cuda_runtime.h>
#include <math_constants.h>
#include <cstdint>

#define N_BOX 1024
#define P_PTS 4096
#define NTHREADS 256
#define NWARPS (NTHREADS / 32)
#define SPLIT 4
#define NBLOCKS (N_BOX * SPLIT)              /* 4096 */
#define VEC_PER_BLK (P_PTS / 2 / SPLIT)      /* 512 float4-pairs -> 1024 pts */
#define ITERS (VEC_PER_BLK / NTHREADS)       /* 2 -> 4 pts/thread */

#define PTS_BYTES (VEC_PER_BLK * 16)         /* 8192  */
#define DEN_BYTES (VEC_PER_BLK * 8)          /* 4096  */
#define TX_BYTES  (PTS_BYTES + DEN_BYTES)    /* 12288 */

__device__ float g_psum[NBLOCKS];
__device__ int   g_pcnt[NBLOCKS];
__device__ int   g_count;   // zero-init at load; reset by last block each launch

__device__ __forceinline__ float frcp_approx(float x) {
    float r;
    asm("rcp.approx.f32 %0, %1;" : "=f"(r) : "f"(x));
    return r;
}

__device__ __forceinline__ uint32_t smem_u32(const void* p) {
    uint32_t a;
    asm("{ .reg .u64 t; cvta.to.shared.u64 t, %1; cvt.u32.u64 %0, t; }"
        : "=r"(a) : "l"(p));
    return a;
}

__global__ __launch_bounds__(NTHREADS, 8)
void wdm3d_fused_kernel(const float*  __restrict__ wl,
                        const float*  __restrict__ Ry,
                        const float4* __restrict__ points4,
                        const float2* __restrict__ density2,
                        const float*  __restrict__ center,
                        float* __restrict__ out)
{
    const int blk  = blockIdx.x;
    const int n    = blk >> 2;        // box index
    const int part = blk & 3;         // quarter of the point set
    const unsigned full = 0xFFFFFFFFu;
    const int tid  = threadIdx.x;

    __shared__ __align__(16) float4 s_pts[VEC_PER_BLK];
    __shared__ __align__(16) float2 s_den[VEC_PER_BLK];
    __shared__ __align__(8)  unsigned long long s_mbar;
    __shared__ bool s_last;

    const size_t basev = (size_t)n * (P_PTS / 2) + (size_t)part * VEC_PER_BLK;
    const uint32_t mbar = smem_u32(&s_mbar);

    // ---------------- bulk-copy the whole chunk into smem (one TMA stream)
    if (tid == 0) {
        asm volatile("mbarrier.init.shared.b64 [%0], %1;"
                     :: "r"(mbar), "r"(1) : "memory");
    }
    __syncthreads();
    if (tid == 0) {
        asm volatile("mbarrier.arrive.expect_tx.shared.b64 _, [%0], %1;"
                     :: "r"(mbar), "r"((uint32_t)TX_BYTES) : "memory");
        asm volatile(
            "cp.async.bulk.shared::cluster.global.mbarrier::complete_tx::bytes "
            "[%0], [%1], %2, [%3];"
            :: "r"(smem_u32(s_pts)), "l"(points4 + basev),
               "r"((uint32_t)PTS_BYTES), "r"(mbar) : "memory");
        asm volatile(
            "cp.async.bulk.shared::cluster.global.mbarrier::complete_tx::bytes "
            "[%0], [%1], %2, [%3];"
            :: "r"(smem_u32(s_den)), "l"(density2 + basev),
               "r"((uint32_t)DEN_BYTES), "r"(mbar) : "memory");
    }

    // ---------------- per-box constants: slab model (runs in TMA shadow)
    // Box frame: u-axis = x rotated by Ry. Line L(t) = t*(px,py).
    // Edge crossings: t = (cu ± l/2)/au, (cv ± w/2)/av.
    // mask-count==2 <=> slab overlap tE < tX (open)
    // cen = |t|*||p|| -> argmin by |t|;  dis = |t-1| * (|px|+|py|)
    float cr, sr, Cu0, Cu1, Cv0, Cv1;
    {
        const float w   = __ldg(&wl[2 * n]);
        const float l   = __ldg(&wl[2 * n + 1]);
        const float ry  = __ldg(&Ry[n]);
        const float ccx = __ldg(&center[2 * n]);
        const float ccy = __ldg(&center[2 * n + 1]);

        sincosf(ry, &sr, &cr);
        const float cu = ccx * cr + ccy * sr;
        const float cv = ccy * cr - ccx * sr;
        const float hl = 0.5f * l;
        const float hw = 0.5f * w;
        Cu0 = cu - hl; Cu1 = cu + hl;
        Cv0 = cv - hw; Cv1 = cv + hw;
    }

    // ---------------- wait for the bulk copy (acquire)
    {
        uint32_t done;
        asm volatile(
            "{\n\t.reg .pred p;\n\t"
            "mbarrier.try_wait.parity.acquire.cta.shared::cta.b64 p, [%1], %2;\n\t"
            "selp.b32 %0, 1, 0, p;\n\t}"
            : "=r"(done) : "r"(mbar), "r"(0u) : "memory");
        if (!done) {
            asm volatile(
                "{\n\t.reg .pred P1;\n\t"
                "WAIT_LOOP_%=:\n\t"
                "mbarrier.try_wait.parity.acquire.cta.shared::cta.b64 P1, [%0], %1, 0x989680;\n\t"
                "@P1 bra.uni WAIT_DONE_%=;\n\t"
                "bra.uni WAIT_LOOP_%=;\n\t"
                "WAIT_DONE_%=:\n\t}"
                :: "r"(mbar), "r"(0u) : "memory");
        }
    }

    float sum = 0.0f;
    int   cnt = 0;

#define PROCESS_POINT(PX_, PY_, DENS_)                                          \
    do {                                                                        \
        const float px = ((PX_) == 0.0f) ? 0.0001f : (PX_);                     \
        const float py = (PY_);                                                 \
        const float au = fmaf(px, cr, py * sr);                                 \
        const float av = fmaf(py, cr, -px * sr);                                \
        const float ru = frcp_approx(au);                                       \
        const float rv = frcp_approx(av);                                       \
        const float a0 = Cu0 * ru, a1 = Cu1 * ru;                               \
        const float b0 = Cv0 * rv, b1 = Cv1 * rv;                               \
        const float tE = fmaxf(fminf(a0, a1), fminf(b0, b1));                   \
        const float tX = fminf(fmaxf(a0, a1), fmaxf(b0, b1));                   \
        const bool hit = tE < tX;                                               \
        const float tsel = (fabsf(tE) <= fabsf(tX)) ? tE : tX;                  \
        if (hit) {                                                              \
            const float dsel = (fabsf(px) + fabsf(py)) * fabsf(tsel - 1.0f);    \
            sum += dsel * frcp_approx(DENS_);                                   \
            cnt += 1;                                                           \
        }                                                                       \
    } while (0)

#pragma unroll
    for (int it = 0; it < ITERS; it++) {
        const float4 p = s_pts[tid + it * NTHREADS];
        const float2 d = s_den[tid + it * NTHREADS];
        PROCESS_POINT(p.x, p.y, d.x);
        PROCESS_POINT(p.z, p.w, d.y);
    }

    // ---------------- block reduction
#pragma unroll
    for (int off = 16; off > 0; off >>= 1) {
        sum += __shfl_down_sync(full, sum, off);
        cnt += __shfl_down_sync(full, cnt, off);
    }

    __shared__ float s_sum[NWARPS];
    __shared__ int   s_cnt[NWARPS];
    const int warp = tid >> 5;
    const int lane = tid & 31;
    if (lane == 0) { s_sum[warp] = sum; s_cnt[warp] = cnt; }
    __syncthreads();

    if (tid == 0) {
        float fs = 0.0f; int fc = 0;
#pragma unroll
        for (int wi = 0; wi < NWARPS; wi++) { fs += s_sum[wi]; fc += s_cnt[wi]; }
        g_psum[blk] = fs;
        g_pcnt[blk] = fc;
        __threadfence();
        const int prev = atomicAdd(&g_count, 1);
        s_last = (prev == gridDim.x - 1);
    }
    __syncthreads();

    // ---------------- last block: deterministic final reduction over boxes
    if (s_last) {
        float fs = 0.0f;
        int   fv = 0;
#pragma unroll
        for (int jb = 0; jb < N_BOX / NTHREADS; jb++) {
            const int b = tid + jb * NTHREADS;
            float bsum = 0.0f; int bcnt = 0;
#pragma unroll
            for (int q = 0; q < SPLIT; q++) {
                bsum += __ldcg(&g_psum[SPLIT * b + q]);
                bcnt += __ldcg(&g_pcnt[SPLIT * b + q]);
            }
            const bool valid = (bcnt >= 3);
            fs += valid ? (bsum / (float)max(bcnt, 1)) : 0.0f;
            fv += valid ? 1 : 0;
        }
#pragma unroll
        for (int off = 16; off > 0; off >>= 1) {
            fs += __shfl_down_sync(full, fs, off);
            fv += __shfl_down_sync(full, fv, off);
        }
        __shared__ float f_sum[NWARPS];
        __shared__ int   f_cnt[NWARPS];
        if (lane == 0) { f_sum[warp] = fs; f_cnt[warp] = fv; }
        __syncthreads();
        if (tid == 0) {
            float ts = 0.0f; int tv = 0;
#pragma unroll
            for (int wi = 0; wi < NWARPS; wi++) { ts += f_sum[wi]; tv += f_cnt[wi]; }
            out[0] = ts / (float)max(tv, 1);
            g_count = 0;
        }
    }
}

extern "C" void kernel_launch(void* const* d_in, const int* in_sizes, int n_in,
                              void* d_out, int out_size)
{
    const float*  wl       = (const float*)d_in[0];
    const float*  Ry       = (const float*)d_in[1];
    const float4* points4  = (const float4*)d_in[2];
    const float2* density2 = (const float2*)d_in[3];
    const float*  center   = (const float*)d_in[4];
    float* out = (float*)d_out;

    wdm3d_fused_kernel<<<NBLOCKS, NTHREADS>>>(wl, Ry, points4, density2, center, out);
}